// round 10
// baseline (speedup 1.0000x reference)
#include <cuda_runtime.h>
#include <cuda_bf16.h>
#include <math_constants.h>
#include <cstdint>

#define NN 512
#define BB 4
#define HH 4
#define FF 64
#define NCHT 8      // T-partial chunks = 8 m-tiles of 64 rows

// ---------------- scratch (device globals; no allocation) ----------------
__device__ float g_d[NN];
__device__ float g_c[NN];
__device__ float g_cpart[128 * NN];
__device__ float g_nor[NN * NN];
__device__ __nv_bfloat16 g_qh[BB * HH * NN * FF];  // q hi (pre-scaled 1/8)
__device__ __nv_bfloat16 g_ql[BB * HH * NN * FF];  // q lo
__device__ __nv_bfloat16 g_kh[BB * HH * NN * FF];  // k hi
__device__ __nv_bfloat16 g_kl[BB * HH * NN * FF];  // k lo
__device__ float g_Tpart[NCHT * BB * HH * NN];
__device__ float g_T[BB * HH * NN];

// ---------------- f32x2 helpers ----------------
__device__ __forceinline__ unsigned long long f2pack(float a, float b) {
    unsigned long long r;
    asm("mov.b64 %0,{%1,%2};" : "=l"(r) : "f"(a), "f"(b));
    return r;
}
__device__ __forceinline__ void f2fma(unsigned long long& d, unsigned long long a,
                                      unsigned long long b) {
    asm("fma.rn.f32x2 %0,%1,%2,%0;" : "+l"(d) : "l"(a), "l"(b));
}
__device__ __forceinline__ void f2unpack(unsigned long long v, float& a, float& b) {
    asm("mov.b64 {%0,%1},%2;" : "=f"(a), "=f"(b) : "l"(v));
}

// ---------------- HMMA m16n8k16 bf16 -> f32 ----------------
__device__ __forceinline__ void mma16816(float d[4], const uint32_t a[4],
                                         const uint32_t b[2]) {
    asm volatile(
        "mma.sync.aligned.m16n8k16.row.col.f32.bf16.bf16.f32 "
        "{%0,%1,%2,%3}, {%4,%5,%6,%7}, {%8,%9}, {%0,%1,%2,%3};"
        : "+f"(d[0]), "+f"(d[1]), "+f"(d[2]), "+f"(d[3])
        : "r"(a[0]), "r"(a[1]), "r"(a[2]), "r"(a[3]), "r"(b[0]), "r"(b[1]));
}

__device__ __forceinline__ uint32_t smem_u32(const void* p) {
    uint32_t r;
    asm("{ .reg .u64 t; cvta.to.shared.u64 t, %1; cvt.u32.u64 %0, t; }"
        : "=r"(r) : "l"(p));
    return r;
}
__device__ __forceinline__ void ldsm4(uint32_t r[4], uint32_t addr) {
    asm volatile("ldmatrix.sync.aligned.m8n8.x4.shared.b16 {%0,%1,%2,%3}, [%4];"
                 : "=r"(r[0]), "=r"(r[1]), "=r"(r[2]), "=r"(r[3]) : "r"(addr));
}

// ---------------- cp.async + mbarrier ----------------
#define CP16(dst, src) \
    asm volatile("cp.async.cg.shared.global [%0], [%1], 16;" \
                 :: "r"(dst), "l"(__cvta_generic_to_global(src)) : "memory")
#define CP_ARRIVE(mb) \
    asm volatile("cp.async.mbarrier.arrive.noinc.shared.b64 [%0];" :: "r"(mb) : "memory")
#define MBAR_INIT(mb, n) \
    asm volatile("mbarrier.init.shared.b64 [%0], %1;" :: "r"(mb), "r"((uint32_t)(n)) : "memory")
#define MBAR_WAIT(mb, ph) do { \
    asm volatile( \
        "{\n\t.reg .pred P1;\n\t" \
        "WAIT_LOOP_%=:\n\t" \
        "mbarrier.try_wait.parity.acquire.cta.shared::cta.b64 P1, [%0], %1, 0x989680;\n\t" \
        "@P1 bra.uni WAIT_DONE_%=;\n\t" \
        "bra.uni WAIT_LOOP_%=;\n\t" \
        "WAIT_DONE_%=:\n\t}" \
        :: "r"(mb), "r"((uint32_t)(ph)) : "memory"); \
} while (0)

__device__ __forceinline__ float blockReduceSum256(float v, float* red) {
    #pragma unroll
    for (int o = 16; o; o >>= 1) v += __shfl_xor_sync(0xffffffffu, v, o);
    int wid = threadIdx.x >> 5, lane = threadIdx.x & 31;
    if (lane == 0) red[wid] = v;
    __syncthreads();
    float r = (threadIdx.x < 8) ? red[threadIdx.x] : 0.f;
    if (wid == 0) {
        #pragma unroll
        for (int o = 4; o; o >>= 1) r += __shfl_xor_sync(0xffffffffu, r, o);
    }
    return r;
}

// ---------------- K1a: degrees ----------------
__global__ void k_deg(const float* __restrict__ adj) {
    __shared__ float red[8];
    int i = blockIdx.x;
    float s = 0.f;
    for (int j = threadIdx.x; j < NN; j += 256) s += adj[i * NN + j];
    s = blockReduceSum256(s, red);
    if (threadIdx.x == 0) g_d[i] = rsqrtf(s + 1.0f);
}

// ---------------- K1b+K2 fused: nor (blocks 0..127) | proj (blocks 128..383)
__global__ __launch_bounds__(512) void k_nor_proj(const float* __restrict__ adj,
                                                  const float* __restrict__ x,
                                                  const float* __restrict__ Wq,
                                                  const float* __restrict__ bq,
                                                  const float* __restrict__ Wk,
                                                  const float* __restrict__ bk) {
    __shared__ float xs[64][65];
    __shared__ float ws[64][64];

    if (blockIdx.x < 128) {
        // ---- normalized adjacency + col-sum partials ----
        const int bk_ = blockIdx.x;
        const int j = threadIdx.x;
        const float dj = g_d[j];
        float s = 0.f;
        #pragma unroll
        for (int r = 0; r < 4; r++) {
            int i = bk_ * 4 + r;
            float a = adj[i * NN + j] + (i == j ? 1.0f : 0.0f);
            float v = g_d[i] * dj * a;
            g_nor[i * NN + j] = v;
            s += v;
        }
        g_cpart[bk_ * NN + j] = s;
        return;
    }

    // ---- q/k projection -> bf16 hi/lo (threads 0..255 active) ----
    const int pb = blockIdx.x - 128;       // 0..255
    const int px = pb & 31, by = pb >> 5;  // 32 row-tiles x 8
    const bool isK = by >= 4;
    const float* W = isK ? Wk : Wq;
    const float* bias = isK ? bk : bq;
    const int h = isK ? by - 4 : by;
    const int c0 = h * 64;
    const int rowBase = px * 64;
    const int b = rowBase >> 9;
    const int bh = b * HH + h;
    const int nb = rowBase & 511;

    const int t = threadIdx.x;
    if (t < 256) {
        const int tx = t & 15;
        #pragma unroll
        for (int i = 0; i < 4; i++) {
            int lin4 = t + i * 256;
            int r = lin4 >> 4, c4 = (lin4 & 15) * 4;
            float4 v = *(const float4*)(x + rowBase * 64 + lin4 * 4);
            xs[r][c4] = v.x; xs[r][c4 + 1] = v.y; xs[r][c4 + 2] = v.z; xs[r][c4 + 3] = v.w;
            *(float4*)&ws[r][c4] = *(const float4*)(W + r * 256 + c0 + c4);
        }
        (void)tx;
    }
    __syncthreads();
    if (t >= 256) return;

    const int tx = t & 15, ty = t >> 4;
    float acc[4][4];
    #pragma unroll
    for (int i = 0; i < 4; i++)
        #pragma unroll
        for (int jj = 0; jj < 4; jj++) acc[i][jj] = 0.f;

    #pragma unroll 8
    for (int k = 0; k < 64; k++) {
        float a0 = xs[4 * ty + 0][k];
        float a1 = xs[4 * ty + 1][k];
        float a2 = xs[4 * ty + 2][k];
        float a3 = xs[4 * ty + 3][k];
        float4 bv = *(float4*)&ws[k][4 * tx];
        acc[0][0] += a0 * bv.x; acc[0][1] += a0 * bv.y; acc[0][2] += a0 * bv.z; acc[0][3] += a0 * bv.w;
        acc[1][0] += a1 * bv.x; acc[1][1] += a1 * bv.y; acc[1][2] += a1 * bv.z; acc[1][3] += a1 * bv.w;
        acc[2][0] += a2 * bv.x; acc[2][1] += a2 * bv.y; acc[2][2] += a2 * bv.z; acc[2][3] += a2 * bv.w;
        acc[3][0] += a3 * bv.x; acc[3][1] += a3 * bv.y; acc[3][2] += a3 * bv.z; acc[3][3] += a3 * bv.w;
    }

    float4 bb = *(const float4*)&bias[c0 + 4 * tx];
    const float sc = isK ? 1.0f : 0.125f;
    __nv_bfloat16* dh = isK ? g_kh : g_qh;
    __nv_bfloat16* dl = isK ? g_kl : g_ql;
    #pragma unroll
    for (int rr = 0; rr < 4; rr++) {
        int n = nb + 4 * ty + rr;
        size_t o = (size_t)(bh * NN + n) * FF + 4 * tx;
        float v0 = (acc[rr][0] + bb.x) * sc;
        float v1 = (acc[rr][1] + bb.y) * sc;
        float v2 = (acc[rr][2] + bb.z) * sc;
        float v3 = (acc[rr][3] + bb.w) * sc;
        __nv_bfloat16 h0 = __float2bfloat16(v0), h1 = __float2bfloat16(v1);
        __nv_bfloat16 h2 = __float2bfloat16(v2), h3 = __float2bfloat16(v3);
        *(__nv_bfloat162*)&dh[o]     = __halves2bfloat162(h0, h1);
        *(__nv_bfloat162*)&dh[o + 2] = __halves2bfloat162(h2, h3);
        *(__nv_bfloat162*)&dl[o] = __halves2bfloat162(
            __float2bfloat16(v0 - __bfloat162float(h0)),
            __float2bfloat16(v1 - __bfloat162float(h1)));
        *(__nv_bfloat162*)&dl[o + 2] = __halves2bfloat162(
            __float2bfloat16(v2 - __bfloat162float(h2)),
            __float2bfloat16(v3 - __bfloat162float(h3)));
    }
}

// ---------------- K3: HMMA scores, cp.async-pipelined -------------------
// grid (8 mtiles, H, B) = 128 blocks, 512 threads (16 warps).
// Full k (hi+lo) staged once in 4 x 128-row chunks; warp (m,cs) owns column
// chunk cs and waits only its own mbarrier -> no block-wide fill barrier.
// smem: qh 9216B | kh 73728B | kl 73728B | expb bf16 64x520 = 66560B
#define ATTN_DSM 223232
__global__ __launch_bounds__(512, 1) void k_attn_mma() {
    extern __shared__ __align__(16) char dsm[];
    __nv_bfloat16* qh_s = (__nv_bfloat16*)dsm;
    __nv_bfloat16* kh_s = (__nv_bfloat16*)(dsm + 9216);
    __nv_bfloat16* kl_s = (__nv_bfloat16*)(dsm + 82944);
    __nv_bfloat16* expb = (__nv_bfloat16*)(dsm + 156672);

    __shared__ unsigned long long mbars[4];
    __shared__ float rsum[4][64];
    __shared__ float rinv[64];

    const int mtile = blockIdx.x, h = blockIdx.y, b = blockIdx.z;
    const int bh = b * HH + h;
    const int iBase = mtile * 64;
    const int tid = threadIdx.x;
    const int w = tid >> 5, lane = tid & 31;
    const int mrow = (w >> 2) * 16;     // warp's 16-row strip
    const int cs = w & 3;               // warp's 128-col chunk
    const int r = lane >> 2, c = lane & 3;

    const uint32_t qh_b = smem_u32(qh_s);
    const uint32_t kh_b = smem_u32(kh_s);
    const uint32_t kl_b = smem_u32(kl_s);

    if (tid < 4) MBAR_INIT(smem_u32(&mbars[tid]), 512);

    // q hi fill: 512 uint4, one per thread
    {
        const uint4* sh = (const uint4*)(g_qh + (size_t)(bh * NN + iBase) * FF);
        int row = tid >> 3, c8 = tid & 7;
        *(uint4*)&qh_s[row * 72 + c8 * 8] = sh[tid];
    }
    __syncthreads();   // mbar init + q stores visible

    // k fills: 4 chunks x 128 rows, cp.async, per-chunk mbar arrive
    {
        const char* khg = (const char*)(g_kh + (size_t)bh * NN * FF);
        const char* klg = (const char*)(g_kl + (size_t)bh * NN * FF);
        #pragma unroll
        for (int ch = 0; ch < 4; ch++) {
            #pragma unroll
            for (int i = 0; i < 2; i++) {
                int idx = tid + i * 512;              // 0..1023
                int row = ch * 128 + (idx >> 3), c8 = idx & 7;
                CP16(kh_b + (uint32_t)(row * 144 + c8 * 16), khg + row * 128 + c8 * 16);
                CP16(kl_b + (uint32_t)(row * 144 + c8 * 16), klg + row * 128 + c8 * 16);
            }
            CP_ARRIVE(smem_u32(&mbars[ch]));
        }
    }

    // A frags: qh via ldmatrix, ql direct from global (one-time)
    uint32_t qhA[4][4], qlA[4][4];
    {
        const int arow = mrow + (lane & 7) + ((lane >> 3) & 1) * 8;
        const uint32_t aoff = (uint32_t)(arow * 72 + (lane >> 4) * 8) * 2;
        #pragma unroll
        for (int kt = 0; kt < 4; kt++) ldsm4(qhA[kt], qh_b + aoff + kt * 32);
        const __nv_bfloat16* qlg = g_ql + (size_t)(bh * NN + iBase) * FF;
        #pragma unroll
        for (int kt = 0; kt < 4; kt++) {
            int col = kt * 16 + 2 * c;
            qlA[kt][0] = *(const uint32_t*)&qlg[(mrow + r) * 64 + col];
            qlA[kt][1] = *(const uint32_t*)&qlg[(mrow + r + 8) * 64 + col];
            qlA[kt][2] = *(const uint32_t*)&qlg[(mrow + r) * 64 + col + 8];
            qlA[kt][3] = *(const uint32_t*)&qlg[(mrow + r + 8) * 64 + col + 8];
        }
    }

    // wait only this warp's chunk
    MBAR_WAIT(smem_u32(&mbars[cs]), 0);

    float rs0 = 0.f, rs1 = 0.f;
    const int brow0 = cs * 128 + (lane & 7);
    const uint32_t boff_lane = (uint32_t)((lane >> 3) * 16);

    #pragma unroll 2
    for (int nt = 0; nt < 16; nt++) {
        const uint32_t bb = (uint32_t)((brow0 + nt * 8) * 144) + boff_lane;
        uint32_t khx[8], klx[8];
        ldsm4(khx, kh_b + bb);
        ldsm4(khx + 4, kh_b + bb + 64);
        ldsm4(klx, kl_b + bb);
        ldsm4(klx + 4, kl_b + bb + 64);

        float d0[4] = {0.f, 0.f, 0.f, 0.f};
        float d1[4] = {0.f, 0.f, 0.f, 0.f};
        float d2[4] = {0.f, 0.f, 0.f, 0.f};
        #pragma unroll
        for (int kt = 0; kt < 4; kt++) {
            mma16816(d0, qhA[kt], khx + 2 * kt);
            mma16816(d1, qhA[kt], klx + 2 * kt);
            mma16816(d2, qlA[kt], khx + 2 * kt);
        }
        float e0 = __expf(d0[0] + d1[0] + d2[0]);
        float e1 = __expf(d0[1] + d1[1] + d2[1]);
        float e2 = __expf(d0[2] + d1[2] + d2[2]);
        float e3 = __expf(d0[3] + d1[3] + d2[3]);
        rs0 += e0 + e1;
        rs1 += e2 + e3;
        int gcol = cs * 128 + nt * 8 + 2 * c;
        *(__nv_bfloat162*)&expb[(mrow + r) * 520 + gcol] =
            __halves2bfloat162(__float2bfloat16(e0), __float2bfloat16(e1));
        *(__nv_bfloat162*)&expb[(mrow + r + 8) * 520 + gcol] =
            __halves2bfloat162(__float2bfloat16(e2), __float2bfloat16(e3));
    }

    // rowsums: quad reduce, combine 4 col chunks
    rs0 += __shfl_xor_sync(0xffffffffu, rs0, 1);
    rs0 += __shfl_xor_sync(0xffffffffu, rs0, 2);
    rs1 += __shfl_xor_sync(0xffffffffu, rs1, 1);
    rs1 += __shfl_xor_sync(0xffffffffu, rs1, 2);
    if ((lane & 3) == 0) {
        rsum[cs][mrow + r] = rs0;
        rsum[cs][mrow + r + 8] = rs1;
    }
    __syncthreads();
    if (tid < 64)
        rinv[tid] = 1.0f / (rsum[0][tid] + rsum[1][tid] + rsum[2][tid] + rsum[3][tid]);
    __syncthreads();

    // T partial: one column per thread, dual chains
    {
        const float* np = g_nor + (size_t)iBase * NN;
        float a0 = 0.f, a1 = 0.f;
        #pragma unroll 8
        for (int i = 0; i < 64; i += 2) {
            a0 += np[i * NN + tid] *
                  (__bfloat162float(expb[i * 520 + tid]) * rinv[i]);
            a1 += np[(i + 1) * NN + tid] *
                  (__bfloat162float(expb[(i + 1) * 520 + tid]) * rinv[i + 1]);
        }
        g_Tpart[mtile * (BB * HH * NN) + bh * NN + tid] = a0 + a1;
    }
}

// ---------------- K3b: reduce T partials + column sums c ----------------
__global__ void k_red() {
    if (blockIdx.x < 16) {
        int v = blockIdx.x * 512 + threadIdx.x;
        float s = 0.f;
        #pragma unroll
        for (int ch = 0; ch < NCHT; ch++) s += g_Tpart[ch * (BB * HH * NN) + v];
        g_T[v] = s;
    } else {
        int j = threadIdx.x;
        float s = 0.f;
        #pragma unroll
        for (int p = 0; p < 128; p++) s += g_cpart[p * NN + j];
        g_c[j] = s;
    }
}

// ---------------- K4: out = relu((noradj @ (x*S)) @ Wfc + bfc), fused ----
__global__ __launch_bounds__(512) void k_out(const float* __restrict__ x,
                                             const float* __restrict__ Wlin,
                                             const float* __restrict__ blin,
                                             const float* __restrict__ Wfc,
                                             const float* __restrict__ bfc,
                                             float* __restrict__ out) {
    const int iBase = blockIdx.x * 16;
    const int b = blockIdx.y;
    const int t = threadIdx.x;
    const int il = t >> 5;
    const int f2 = (t & 31) * 2;

    __shared__ float sxs[32][64];
    __shared__ float nrs[32][17];
    __shared__ float wfcs[64 * 64];
    __shared__ float tmp[16][66];
    __shared__ float Ts[HH * NN];
    __shared__ float cs[NN];
    __shared__ float wlins[HH][64];
    __shared__ float blins[64];

    #pragma unroll
    for (int i = 0; i < 2; i++) ((float4*)wfcs)[t + i * 512] = ((const float4*)Wfc)[t + i * 512];
    ((float4*)Ts)[t] = ((const float4*)(g_T + b * HH * NN))[t];
    if (t < 128) ((float4*)cs)[t] = ((const float4*)g_c)[t];
    if (t < 64)  ((float4*)wlins)[t] = ((const float4*)Wlin)[t];
    if (t < 16)  ((float4*)blins)[t] = ((const float4*)blin)[t];
    __syncthreads();

    unsigned long long acc = 0ull;
    for (int j0 = 0; j0 < NN; j0 += 32) {
        {
            int jj = t >> 4, f4 = (t & 15) * 4;
            int jg = j0 + jj;
            float4 xv = *(const float4*)(x + ((b * NN) + jg) * FF + f4);
            float4 bl = *(const float4*)&blins[f4];
            float cj = cs[jg];
            float4 s4;
            s4.x = cj * bl.x; s4.y = cj * bl.y; s4.z = cj * bl.z; s4.w = cj * bl.w;
            #pragma unroll
            for (int hh = 0; hh < HH; hh++) {
                float tv = Ts[hh * NN + jg];
                float4 wl = *(const float4*)&wlins[hh][f4];
                s4.x += tv * wl.x; s4.y += tv * wl.y; s4.z += tv * wl.z; s4.w += tv * wl.w;
            }
            *(float4*)&sxs[jj][f4] =
                make_float4(xv.x * s4.x, xv.y * s4.y, xv.z * s4.z, xv.w * s4.w);
            int ii = t >> 5, jjn = t & 31;
            nrs[jjn][ii] = g_nor[(iBase + ii) * NN + j0 + jjn];
        }
        __syncthreads();
        #pragma unroll
        for (int jj = 0; jj < 32; jj++) {
            float nrv = nrs[jj][il];
            f2fma(acc, f2pack(nrv, nrv), *(const unsigned long long*)&sxs[jj][f2]);
        }
        __syncthreads();
    }

    float v0, v1;
    f2unpack(acc, v0, v1);
    tmp[il][f2] = v0; tmp[il][f2 + 1] = v1;
    __syncthreads();

    unsigned long long o0 = f2pack(bfc[f2], bfc[f2 + 1]);
    #pragma unroll
    for (int ff = 0; ff < 64; ff++) {
        float tv = tmp[il][ff];
        f2fma(o0, f2pack(tv, tv), *(const unsigned long long*)&wfcs[ff * 64 + f2]);
    }
    float r0, r1;
    f2unpack(o0, r0, r1);
    *(float2*)&out[((b * NN) + iBase + il) * FF + f2] =
        make_float2(fmaxf(r0, 0.f), fmaxf(r1, 0.f));
}

// ---------------- launch ----------------
extern "C" void kernel_launch(void* const* d_in, const int* in_sizes, int n_in,
                              void* d_out, int out_size) {
    const float* x    = (const float*)d_in[0];
    const float* adj  = (const float*)d_in[1];
    const float* Wq   = (const float*)d_in[2];
    const float* bq   = (const float*)d_in[3];
    const float* Wk   = (const float*)d_in[4];
    const float* bk   = (const float*)d_in[5];
    const float* Wlin = (const float*)d_in[6];
    const float* blin = (const float*)d_in[7];
    const float* Wfc  = (const float*)d_in[8];
    const float* bfc  = (const float*)d_in[9];
    float* out = (float*)d_out;

    static int attr_set = 0;
    if (!attr_set) {
        cudaFuncSetAttribute(k_attn_mma,
                             cudaFuncAttributeMaxDynamicSharedMemorySize, ATTN_DSM);
        attr_set = 1;
    }

    k_deg<<<NN, 256>>>(adj);
    k_nor_proj<<<384, 512>>>(adj, x, Wq, bq, Wk, bk);
    k_attn_mma<<<dim3(8, HH, BB), 512, ATTN_DSM>>>();
    k_red<<<17, 512>>>();
    k_out<<<dim3(32, BB), 512>>>(x, Wlin, blin, Wfc, bfc, out);
}

// round 11
// speedup vs baseline: 1.1925x; 1.1925x over previous
#include <cuda_runtime.h>
#include <cuda_bf16.h>
#include <math_constants.h>
#include <cstdint>

#define NN 512
#define BB 4
#define HH 4
#define FF 64
#define NCHT 8      // T-partial chunks = 8 m-tiles of 64 rows

// ---------------- scratch (device globals; no allocation) ----------------
__device__ float g_d[NN];
__device__ float g_cpart[32 * NN];
__device__ float g_nor[NN * NN];
__device__ __nv_bfloat16 g_qh[BB * HH * NN * FF];  // q hi (pre-scaled 1/8)
__device__ __nv_bfloat16 g_ql[BB * HH * NN * FF];  // q lo
__device__ __nv_bfloat16 g_kh[BB * HH * NN * FF];  // k hi
__device__ __nv_bfloat16 g_kl[BB * HH * NN * FF];  // k lo
__device__ float g_Tpart[NCHT * BB * HH * NN];

// ---------------- f32x2 helpers ----------------
__device__ __forceinline__ unsigned long long f2pack(float a, float b) {
    unsigned long long r;
    asm("mov.b64 %0,{%1,%2};" : "=l"(r) : "f"(a), "f"(b));
    return r;
}
__device__ __forceinline__ void f2fma(unsigned long long& d, unsigned long long a,
                                      unsigned long long b) {
    asm("fma.rn.f32x2 %0,%1,%2,%0;" : "+l"(d) : "l"(a), "l"(b));
}
__device__ __forceinline__ void f2unpack(unsigned long long v, float& a, float& b) {
    asm("mov.b64 {%0,%1},%2;" : "=f"(a), "=f"(b) : "l"(v));
}

// ---------------- HMMA m16n8k16 bf16 -> f32 ----------------
__device__ __forceinline__ void mma16816(float d[4], const uint32_t a[4],
                                         const uint32_t b[2]) {
    asm volatile(
        "mma.sync.aligned.m16n8k16.row.col.f32.bf16.bf16.f32 "
        "{%0,%1,%2,%3}, {%4,%5,%6,%7}, {%8,%9}, {%0,%1,%2,%3};"
        : "+f"(d[0]), "+f"(d[1]), "+f"(d[2]), "+f"(d[3])
        : "r"(a[0]), "r"(a[1]), "r"(a[2]), "r"(a[3]), "r"(b[0]), "r"(b[1]));
}

__device__ __forceinline__ uint32_t smem_u32(const void* p) {
    uint32_t r;
    asm("{ .reg .u64 t; cvta.to.shared.u64 t, %1; cvt.u32.u64 %0, t; }"
        : "=r"(r) : "l"(p));
    return r;
}
__device__ __forceinline__ void ldsm4(uint32_t r[4], uint32_t addr) {
    asm volatile("ldmatrix.sync.aligned.m8n8.x4.shared.b16 {%0,%1,%2,%3}, [%4];"
                 : "=r"(r[0]), "=r"(r[1]), "=r"(r[2]), "=r"(r[3]) : "r"(addr));
}

// ---------------- cp.async + mbarrier ----------------
#define CP16(dst, src) \
    asm volatile("cp.async.cg.shared.global [%0], [%1], 16;" \
                 :: "r"(dst), "l"(__cvta_generic_to_global(src)) : "memory")
#define CP_ARRIVE(mb) \
    asm volatile("cp.async.mbarrier.arrive.noinc.shared.b64 [%0];" :: "r"(mb) : "memory")
#define MBAR_INIT(mb, n) \
    asm volatile("mbarrier.init.shared.b64 [%0], %1;" :: "r"(mb), "r"((uint32_t)(n)) : "memory")
#define MBAR_WAIT(mb, ph) do { \
    asm volatile( \
        "{\n\t.reg .pred P1;\n\t" \
        "WAIT_LOOP_%=:\n\t" \
        "mbarrier.try_wait.parity.acquire.cta.shared::cta.b64 P1, [%0], %1, 0x989680;\n\t" \
        "@P1 bra.uni WAIT_DONE_%=;\n\t" \
        "bra.uni WAIT_LOOP_%=;\n\t" \
        "WAIT_DONE_%=:\n\t}" \
        :: "r"(mb), "r"((uint32_t)(ph)) : "memory"); \
} while (0)

__device__ __forceinline__ float blockReduceSum256(float v, float* red) {
    #pragma unroll
    for (int o = 16; o; o >>= 1) v += __shfl_xor_sync(0xffffffffu, v, o);
    int wid = threadIdx.x >> 5, lane = threadIdx.x & 31;
    if (lane == 0) red[wid] = v;
    __syncthreads();
    float r = (threadIdx.x < 8) ? red[threadIdx.x] : 0.f;
    if (wid == 0) {
        #pragma unroll
        for (int o = 4; o; o >>= 1) r += __shfl_xor_sync(0xffffffffu, r, o);
    }
    return r;
}

// ---------------- K1a: degrees ----------------
__global__ void k_deg(const float* __restrict__ adj) {
    __shared__ float red[8];
    int i = blockIdx.x;
    float s = 0.f;
    for (int j = threadIdx.x; j < NN; j += 256) s += adj[i * NN + j];
    s = blockReduceSum256(s, red);
    if (threadIdx.x == 0) g_d[i] = rsqrtf(s + 1.0f);
}

// ---------------- K1b+K2 fused: nor (blocks 0..31) | proj (blocks 32..287)
__global__ __launch_bounds__(512) void k_nor_proj(const float* __restrict__ adj,
                                                  const float* __restrict__ x,
                                                  const float* __restrict__ Wq,
                                                  const float* __restrict__ bq,
                                                  const float* __restrict__ Wk,
                                                  const float* __restrict__ bk) {
    __shared__ float xs[64][65];
    __shared__ float ws[64][64];

    if (blockIdx.x < 32) {
        // ---- normalized adjacency + col-sum partials (16 rows/block) ----
        const int bk_ = blockIdx.x;
        const int j = threadIdx.x;
        const float dj = g_d[j];
        float s = 0.f;
        #pragma unroll
        for (int r = 0; r < 16; r++) {
            int i = bk_ * 16 + r;
            float a = adj[i * NN + j] + (i == j ? 1.0f : 0.0f);
            float v = g_d[i] * dj * a;
            g_nor[i * NN + j] = v;
            s += v;
        }
        g_cpart[bk_ * NN + j] = s;
        return;
    }

    // ---- q/k projection -> bf16 hi/lo (threads 0..255 active) ----
    const int pb = blockIdx.x - 32;        // 0..255
    const int px = pb & 31, by = pb >> 5;  // 32 row-tiles x 8
    const bool isK = by >= 4;
    const float* W = isK ? Wk : Wq;
    const float* bias = isK ? bk : bq;
    const int h = isK ? by - 4 : by;
    const int c0 = h * 64;
    const int rowBase = px * 64;
    const int b = rowBase >> 9;
    const int bh = b * HH + h;
    const int nb = rowBase & 511;

    const int t = threadIdx.x;
    if (t < 256) {
        #pragma unroll
        for (int i = 0; i < 4; i++) {
            int lin4 = t + i * 256;
            int r = lin4 >> 4, c4 = (lin4 & 15) * 4;
            float4 v = *(const float4*)(x + rowBase * 64 + lin4 * 4);
            xs[r][c4] = v.x; xs[r][c4 + 1] = v.y; xs[r][c4 + 2] = v.z; xs[r][c4 + 3] = v.w;
            *(float4*)&ws[r][c4] = *(const float4*)(W + r * 256 + c0 + c4);
        }
    }
    __syncthreads();
    if (t >= 256) return;

    const int tx = t & 15, ty = t >> 4;
    float acc[4][4];
    #pragma unroll
    for (int i = 0; i < 4; i++)
        #pragma unroll
        for (int jj = 0; jj < 4; jj++) acc[i][jj] = 0.f;

    #pragma unroll 8
    for (int k = 0; k < 64; k++) {
        float a0 = xs[4 * ty + 0][k];
        float a1 = xs[4 * ty + 1][k];
        float a2 = xs[4 * ty + 2][k];
        float a3 = xs[4 * ty + 3][k];
        float4 bv = *(float4*)&ws[k][4 * tx];
        acc[0][0] += a0 * bv.x; acc[0][1] += a0 * bv.y; acc[0][2] += a0 * bv.z; acc[0][3] += a0 * bv.w;
        acc[1][0] += a1 * bv.x; acc[1][1] += a1 * bv.y; acc[1][2] += a1 * bv.z; acc[1][3] += a1 * bv.w;
        acc[2][0] += a2 * bv.x; acc[2][1] += a2 * bv.y; acc[2][2] += a2 * bv.z; acc[2][3] += a2 * bv.w;
        acc[3][0] += a3 * bv.x; acc[3][1] += a3 * bv.y; acc[3][2] += a3 * bv.z; acc[3][3] += a3 * bv.w;
    }

    float4 bb = *(const float4*)&bias[c0 + 4 * tx];
    const float sc = isK ? 1.0f : 0.125f;
    __nv_bfloat16* dh = isK ? g_kh : g_qh;
    __nv_bfloat16* dl = isK ? g_kl : g_ql;
    #pragma unroll
    for (int rr = 0; rr < 4; rr++) {
        int n = nb + 4 * ty + rr;
        size_t o = (size_t)(bh * NN + n) * FF + 4 * tx;
        float v0 = (acc[rr][0] + bb.x) * sc;
        float v1 = (acc[rr][1] + bb.y) * sc;
        float v2 = (acc[rr][2] + bb.z) * sc;
        float v3 = (acc[rr][3] + bb.w) * sc;
        __nv_bfloat16 h0 = __float2bfloat16(v0), h1 = __float2bfloat16(v1);
        __nv_bfloat16 h2 = __float2bfloat16(v2), h3 = __float2bfloat16(v3);
        *(__nv_bfloat162*)&dh[o]     = __halves2bfloat162(h0, h1);
        *(__nv_bfloat162*)&dh[o + 2] = __halves2bfloat162(h2, h3);
        *(__nv_bfloat162*)&dl[o] = __halves2bfloat162(
            __float2bfloat16(v0 - __bfloat162float(h0)),
            __float2bfloat16(v1 - __bfloat162float(h1)));
        *(__nv_bfloat162*)&dl[o + 2] = __halves2bfloat162(
            __float2bfloat16(v2 - __bfloat162float(h2)),
            __float2bfloat16(v3 - __bfloat162float(h3)));
    }
}

// ---------------- K3: HMMA scores, cp.async-pipelined -------------------
#define ATTN_DSM 223232
__global__ __launch_bounds__(512, 1) void k_attn_mma() {
    extern __shared__ __align__(16) char dsm[];
    __nv_bfloat16* qh_s = (__nv_bfloat16*)dsm;
    __nv_bfloat16* kh_s = (__nv_bfloat16*)(dsm + 9216);
    __nv_bfloat16* kl_s = (__nv_bfloat16*)(dsm + 82944);
    __nv_bfloat16* expb = (__nv_bfloat16*)(dsm + 156672);

    __shared__ unsigned long long mbars[4];
    __shared__ float rsum[4][64];
    __shared__ float rinv[64];

    const int mtile = blockIdx.x, h = blockIdx.y, b = blockIdx.z;
    const int bh = b * HH + h;
    const int iBase = mtile * 64;
    const int tid = threadIdx.x;
    const int w = tid >> 5, lane = tid & 31;
    const int mrow = (w >> 2) * 16;
    const int cs = w & 3;
    const int r = lane >> 2, c = lane & 3;

    const uint32_t qh_b = smem_u32(qh_s);
    const uint32_t kh_b = smem_u32(kh_s);
    const uint32_t kl_b = smem_u32(kl_s);

    if (tid < 4) MBAR_INIT(smem_u32(&mbars[tid]), 512);

    {
        const uint4* sh = (const uint4*)(g_qh + (size_t)(bh * NN + iBase) * FF);
        int row = tid >> 3, c8 = tid & 7;
        *(uint4*)&qh_s[row * 72 + c8 * 8] = sh[tid];
    }
    __syncthreads();

    {
        const char* khg = (const char*)(g_kh + (size_t)bh * NN * FF);
        const char* klg = (const char*)(g_kl + (size_t)bh * NN * FF);
        #pragma unroll
        for (int ch = 0; ch < 4; ch++) {
            #pragma unroll
            for (int i = 0; i < 2; i++) {
                int idx = tid + i * 512;
                int row = ch * 128 + (idx >> 3), c8 = idx & 7;
                CP16(kh_b + (uint32_t)(row * 144 + c8 * 16), khg + row * 128 + c8 * 16);
                CP16(kl_b + (uint32_t)(row * 144 + c8 * 16), klg + row * 128 + c8 * 16);
            }
            CP_ARRIVE(smem_u32(&mbars[ch]));
        }
    }

    uint32_t qhA[4][4], qlA[4][4];
    {
        const int arow = mrow + (lane & 7) + ((lane >> 3) & 1) * 8;
        const uint32_t aoff = (uint32_t)(arow * 72 + (lane >> 4) * 8) * 2;
        #pragma unroll
        for (int kt = 0; kt < 4; kt++) ldsm4(qhA[kt], qh_b + aoff + kt * 32);
        const __nv_bfloat16* qlg = g_ql + (size_t)(bh * NN + iBase) * FF;
        #pragma unroll
        for (int kt = 0; kt < 4; kt++) {
            int col = kt * 16 + 2 * c;
            qlA[kt][0] = *(const uint32_t*)&qlg[(mrow + r) * 64 + col];
            qlA[kt][1] = *(const uint32_t*)&qlg[(mrow + r + 8) * 64 + col];
            qlA[kt][2] = *(const uint32_t*)&qlg[(mrow + r) * 64 + col + 8];
            qlA[kt][3] = *(const uint32_t*)&qlg[(mrow + r + 8) * 64 + col + 8];
        }
    }

    MBAR_WAIT(smem_u32(&mbars[cs]), 0);

    float rs0 = 0.f, rs1 = 0.f;
    const int brow0 = cs * 128 + (lane & 7);
    const uint32_t boff_lane = (uint32_t)((lane >> 3) * 16);

    #pragma unroll 2
    for (int nt = 0; nt < 16; nt++) {
        const uint32_t bb = (uint32_t)((brow0 + nt * 8) * 144) + boff_lane;
        uint32_t khx[8], klx[8];
        ldsm4(khx, kh_b + bb);
        ldsm4(khx + 4, kh_b + bb + 64);
        ldsm4(klx, kl_b + bb);
        ldsm4(klx + 4, kl_b + bb + 64);

        float d0[4] = {0.f, 0.f, 0.f, 0.f};
        float d1[4] = {0.f, 0.f, 0.f, 0.f};
        float d2[4] = {0.f, 0.f, 0.f, 0.f};
        #pragma unroll
        for (int kt = 0; kt < 4; kt++) {
            mma16816(d0, qhA[kt], khx + 2 * kt);
            mma16816(d1, qhA[kt], klx + 2 * kt);
            mma16816(d2, qlA[kt], khx + 2 * kt);
        }
        float e0 = __expf(d0[0] + d1[0] + d2[0]);
        float e1 = __expf(d0[1] + d1[1] + d2[1]);
        float e2 = __expf(d0[2] + d1[2] + d2[2]);
        float e3 = __expf(d0[3] + d1[3] + d2[3]);
        rs0 += e0 + e1;
        rs1 += e2 + e3;
        int gcol = cs * 128 + nt * 8 + 2 * c;
        *(__nv_bfloat162*)&expb[(mrow + r) * 520 + gcol] =
            __halves2bfloat162(__float2bfloat16(e0), __float2bfloat16(e1));
        *(__nv_bfloat162*)&expb[(mrow + r + 8) * 520 + gcol] =
            __halves2bfloat162(__float2bfloat16(e2), __float2bfloat16(e3));
    }

    rs0 += __shfl_xor_sync(0xffffffffu, rs0, 1);
    rs0 += __shfl_xor_sync(0xffffffffu, rs0, 2);
    rs1 += __shfl_xor_sync(0xffffffffu, rs1, 1);
    rs1 += __shfl_xor_sync(0xffffffffu, rs1, 2);
    if ((lane & 3) == 0) {
        rsum[cs][mrow + r] = rs0;
        rsum[cs][mrow + r + 8] = rs1;
    }
    __syncthreads();
    if (tid < 64)
        rinv[tid] = 1.0f / (rsum[0][tid] + rsum[1][tid] + rsum[2][tid] + rsum[3][tid]);
    __syncthreads();

    {
        const float* np = g_nor + (size_t)iBase * NN;
        float a0 = 0.f, a1 = 0.f;
        #pragma unroll 8
        for (int i = 0; i < 64; i += 2) {
            a0 += np[i * NN + tid] *
                  (__bfloat162float(expb[i * 520 + tid]) * rinv[i]);
            a1 += np[(i + 1) * NN + tid] *
                  (__bfloat162float(expb[(i + 1) * 520 + tid]) * rinv[i + 1]);
        }
        g_Tpart[mtile * (BB * HH * NN) + bh * NN + tid] = a0 + a1;
    }
}

// ---------------- K4: fused T/c reduce + out GEMMs -----------------------
// grid (32, B), 512 threads = 16 i-rows x 32 f-threads. j tiled by 64.
__global__ __launch_bounds__(512) void k_out(const float* __restrict__ x,
                                             const float* __restrict__ Wlin,
                                             const float* __restrict__ blin,
                                             const float* __restrict__ Wfc,
                                             const float* __restrict__ bfc,
                                             float* __restrict__ out) {
    const int iBase = blockIdx.x * 16;
    const int b = blockIdx.y;
    const int t = threadIdx.x;
    const int il = t >> 5;
    const int f2 = (t & 31) * 2;

    __shared__ float sxs[64][64];    // 16 KB
    __shared__ float nrs[64][17];
    __shared__ float wfcs[64 * 64];  // 16 KB
    __shared__ float tmp[16][66];
    __shared__ float Ts[HH * NN];    // 8 KB
    __shared__ float cs[NN];
    __shared__ float wlins[HH][64];
    __shared__ float blins[64];

    #pragma unroll
    for (int i = 0; i < 2; i++) ((float4*)wfcs)[t + i * 512] = ((const float4*)Wfc)[t + i * 512];
    // inline T reduction (8 chunks)
    #pragma unroll
    for (int i = 0; i < 4; i++) {
        int v = t + i * 512;
        float s = 0.f;
        #pragma unroll
        for (int ch = 0; ch < NCHT; ch++)
            s += g_Tpart[ch * (BB * HH * NN) + b * HH * NN + v];
        Ts[v] = s;
    }
    // inline c reduction (32 partials)
    {
        float s = 0.f;
        #pragma unroll
        for (int p = 0; p < 32; p++) s += g_cpart[p * NN + t];
        cs[t] = s;
    }
    if (t < 64)  ((float4*)wlins)[t] = ((const float4*)Wlin)[t];
    if (t < 16)  ((float4*)blins)[t] = ((const float4*)blin)[t];
    __syncthreads();

    unsigned long long acc = 0ull;
    for (int j0 = 0; j0 < NN; j0 += 64) {
        #pragma unroll
        for (int i = 0; i < 2; i++) {
            int idx = t + i * 512;          // 0..1023
            int jj = idx >> 4, f4 = (idx & 15) * 4;
            int jg = j0 + jj;
            float4 xv = *(const float4*)(x + ((b * NN) + jg) * FF + f4);
            float4 bl = *(const float4*)&blins[f4];
            float cj = cs[jg];
            float4 s4;
            s4.x = cj * bl.x; s4.y = cj * bl.y; s4.z = cj * bl.z; s4.w = cj * bl.w;
            #pragma unroll
            for (int hh = 0; hh < HH; hh++) {
                float tv = Ts[hh * NN + jg];
                float4 wl = *(const float4*)&wlins[hh][f4];
                s4.x += tv * wl.x; s4.y += tv * wl.y; s4.z += tv * wl.z; s4.w += tv * wl.w;
            }
            *(float4*)&sxs[jj][f4] =
                make_float4(xv.x * s4.x, xv.y * s4.y, xv.z * s4.z, xv.w * s4.w);
            int ii = idx >> 6, jjn = idx & 63;
            nrs[jjn][ii] = g_nor[(iBase + ii) * NN + j0 + jjn];
        }
        __syncthreads();
        #pragma unroll
        for (int jj = 0; jj < 64; jj++) {
            float nrv = nrs[jj][il];
            f2fma(acc, f2pack(nrv, nrv), *(const unsigned long long*)&sxs[jj][f2]);
        }
        __syncthreads();
    }

    float v0, v1;
    f2unpack(acc, v0, v1);
    tmp[il][f2] = v0; tmp[il][f2 + 1] = v1;
    __syncthreads();

    unsigned long long o0 = f2pack(bfc[f2], bfc[f2 + 1]);
    #pragma unroll
    for (int ff = 0; ff < 64; ff++) {
        float tv = tmp[il][ff];
        f2fma(o0, f2pack(tv, tv), *(const unsigned long long*)&wfcs[ff * 64 + f2]);
    }
    float r0, r1;
    f2unpack(o0, r0, r1);
    *(float2*)&out[((b * NN) + iBase + il) * FF + f2] =
        make_float2(fmaxf(r0, 0.f), fmaxf(r1, 0.f));
}

// ---------------- launch ----------------
extern "C" void kernel_launch(void* const* d_in, const int* in_sizes, int n_in,
                              void* d_out, int out_size) {
    const float* x    = (const float*)d_in[0];
    const float* adj  = (const float*)d_in[1];
    const float* Wq   = (const float*)d_in[2];
    const float* bq   = (const float*)d_in[3];
    const float* Wk   = (const float*)d_in[4];
    const float* bk   = (const float*)d_in[5];
    const float* Wlin = (const float*)d_in[6];
    const float* blin = (const float*)d_in[7];
    const float* Wfc  = (const float*)d_in[8];
    const float* bfc  = (const float*)d_in[9];
    float* out = (float*)d_out;

    static int attr_set = 0;
    if (!attr_set) {
        cudaFuncSetAttribute(k_attn_mma,
                             cudaFuncAttributeMaxDynamicSharedMemorySize, ATTN_DSM);
        attr_set = 1;
    }

    k_deg<<<NN, 256>>>(adj);
    k_nor_proj<<<288, 512>>>(adj, x, Wq, bq, Wk, bk);
    k_attn_mma<<<dim3(8, HH, BB), 512, ATTN_DSM>>>();
    k_out<<<dim3(32, BB), 512>>>(x, Wlin, blin, Wfc, bfc, out);
}